// round 3
// baseline (speedup 1.0000x reference)
#include <cuda_runtime.h>

// out[128,512] = x[128,1024] @ w[1024,512] + b   (exact algebraic reduction of
// the memristor reference: G_off and the pos/neg relu split cancel in the
// even-odd column subtraction, and K_V * k_g cancels with the final divide).
//
// Single-kernel split-K GEMM with deterministic fixup reduction:
//  - grid (8,2,8) = 128 blocks (one wave), 64x64 tile, K split 8x128.
//  - double-buffered smem, LDG issued before compute (latency hidden),
//    one __syncthreads per K-iteration.
//  - each block stores its partial to static scratch; the last block per tile
//    (atomic ticket) sums all 8 partials in FIXED z order + bias -> out.

#define BATCH 128
#define NIN   1024
#define NOUT  512

#define BM 64
#define BN 64
#define BK 32
#define SPLITK 8
#define KCHUNK (NIN / SPLITK)      // 128
#define NITER  (KCHUNK / BK)       // 4
#define NTILES ((BATCH / BM) * (NOUT / BN))   // 16
#define TILE_ELEMS (BM * BN)       // 4096

__device__ float        g_scratch[NTILES * SPLITK * TILE_ELEMS];  // 2 MB
__device__ unsigned int g_cnt[NTILES];                            // zero-init

__global__ void __launch_bounds__(256, 1)
memristor_gemm_kernel(const float* __restrict__ x,
                      const float* __restrict__ w,
                      const float* __restrict__ bias,
                      float* __restrict__ out) {
    __shared__ float xsT[2][BK][BM + 4];   // x tile, transposed (k-major rows)
    __shared__ float ws [2][BK][BN + 4];   // w tile, natural (k-major rows)
    __shared__ unsigned s_ret;

    const int tid   = threadIdx.x;
    const int tr    = tid >> 4;            // 0..15 -> rows tr*4..tr*4+3
    const int tc    = tid & 15;            // 0..15 -> cols tc*4..tc*4+3
    const int tileX = blockIdx.x;          // 0..7
    const int tileY = blockIdx.y;          // 0..1
    const int z     = blockIdx.z;          // 0..7
    const int tile  = tileY * (NOUT / BN) + tileX;
    const int row0  = tileY * BM;
    const int col0  = tileX * BN;
    const int kbase = z * KCHUNK;

    // x loader: 64 rows x 8 float4 = 512 float4, 2 per thread
    const int lxr = tid >> 2;              // row in tile 0..63
    const int lxj = tid & 3;               // float4 slots lxj and lxj+4
    // w loader: 32 k-rows x 16 float4 = 512 float4, 2 per thread
    const int lwk = tid >> 3;              // k-row 0..31
    const int lwj = tid & 7;               // float4 slots lwj and lwj+8

    const float* xrow = &x[(row0 + lxr) * NIN + kbase];
    const float* wbas = &w[kbase * NOUT + col0];

    // ---- prologue: stage iteration 0 into buffer 0 ----
    {
        float4 v0 = *reinterpret_cast<const float4*>(&xrow[lxj * 4]);
        float4 v1 = *reinterpret_cast<const float4*>(&xrow[(lxj + 4) * 4]);
        int k0 = lxj * 4;
        xsT[0][k0 + 0][lxr] = v0.x;  xsT[0][k0 + 1][lxr] = v0.y;
        xsT[0][k0 + 2][lxr] = v0.z;  xsT[0][k0 + 3][lxr] = v0.w;
        int k1 = (lxj + 4) * 4;
        xsT[0][k1 + 0][lxr] = v1.x;  xsT[0][k1 + 1][lxr] = v1.y;
        xsT[0][k1 + 2][lxr] = v1.z;  xsT[0][k1 + 3][lxr] = v1.w;

        const float* wr = &wbas[lwk * NOUT];
        float4 u0 = *reinterpret_cast<const float4*>(&wr[lwj * 4]);
        float4 u1 = *reinterpret_cast<const float4*>(&wr[(lwj + 8) * 4]);
        *reinterpret_cast<float4*>(&ws[0][lwk][lwj * 4])       = u0;
        *reinterpret_cast<float4*>(&ws[0][lwk][(lwj + 8) * 4]) = u1;
    }
    __syncthreads();

    float acc[4][4] = {};
    float4 nx0, nx1, nu0, nu1;

    #pragma unroll
    for (int s = 0; s < NITER; ++s) {
        const int cur = s & 1;

        // issue next tile's global loads before compute (latency hidden)
        if (s + 1 < NITER) {
            const int ks = (s + 1) * BK;
            nx0 = *reinterpret_cast<const float4*>(&xrow[ks + lxj * 4]);
            nx1 = *reinterpret_cast<const float4*>(&xrow[ks + (lxj + 4) * 4]);
            const float* wr = &wbas[(ks + lwk) * NOUT];
            nu0 = *reinterpret_cast<const float4*>(&wr[lwj * 4]);
            nu1 = *reinterpret_cast<const float4*>(&wr[(lwj + 8) * 4]);
        }

        // ---- 4x4 microtile FMAs over BK ----
        #pragma unroll
        for (int k = 0; k < BK; ++k) {
            float4 a  = *reinterpret_cast<const float4*>(&xsT[cur][k][tr * 4]);
            float4 bv = *reinterpret_cast<const float4*>(&ws[cur][k][tc * 4]);
            acc[0][0] += a.x * bv.x;  acc[0][1] += a.x * bv.y;
            acc[0][2] += a.x * bv.z;  acc[0][3] += a.x * bv.w;
            acc[1][0] += a.y * bv.x;  acc[1][1] += a.y * bv.y;
            acc[1][2] += a.y * bv.z;  acc[1][3] += a.y * bv.w;
            acc[2][0] += a.z * bv.x;  acc[2][1] += a.z * bv.y;
            acc[2][2] += a.z * bv.z;  acc[2][3] += a.z * bv.w;
            acc[3][0] += a.w * bv.x;  acc[3][1] += a.w * bv.y;
            acc[3][2] += a.w * bv.z;  acc[3][3] += a.w * bv.w;
        }

        // stage next tile into the other buffer
        if (s + 1 < NITER) {
            const int nb = cur ^ 1;
            int k0 = lxj * 4;
            xsT[nb][k0 + 0][lxr] = nx0.x;  xsT[nb][k0 + 1][lxr] = nx0.y;
            xsT[nb][k0 + 2][lxr] = nx0.z;  xsT[nb][k0 + 3][lxr] = nx0.w;
            int k1 = (lxj + 4) * 4;
            xsT[nb][k1 + 0][lxr] = nx1.x;  xsT[nb][k1 + 1][lxr] = nx1.y;
            xsT[nb][k1 + 2][lxr] = nx1.z;  xsT[nb][k1 + 3][lxr] = nx1.w;
            *reinterpret_cast<float4*>(&ws[nb][lwk][lwj * 4])       = nu0;
            *reinterpret_cast<float4*>(&ws[nb][lwk][(lwj + 8) * 4]) = nu1;
            __syncthreads();
        }
    }

    // ---- write partial to scratch ----
    float* sc = &g_scratch[(tile * SPLITK + z) * TILE_ELEMS];
    #pragma unroll
    for (int i = 0; i < 4; ++i) {
        float4 v = make_float4(acc[i][0], acc[i][1], acc[i][2], acc[i][3]);
        *reinterpret_cast<float4*>(&sc[(tr * 4 + i) * BN + tc * 4]) = v;
    }
    __threadfence();

    // ---- ticket: last block per tile reduces ----
    if (tid == 0) s_ret = atomicAdd(&g_cnt[tile], 1u);
    __syncthreads();
    if (s_ret != SPLITK - 1) return;
    if (tid == 0) *(volatile unsigned int*)&g_cnt[tile] = 0;  // reset for next launch
    __threadfence();

    // deterministic reduction: bias + sum over z in fixed order
    float4 bias4 = *reinterpret_cast<const float4*>(&bias[col0 + tc * 4]);
    float4 sum[4];
    #pragma unroll
    for (int i = 0; i < 4; ++i) sum[i] = bias4;

    const float* scb = &g_scratch[tile * SPLITK * TILE_ELEMS];
    #pragma unroll
    for (int z2 = 0; z2 < SPLITK; ++z2) {
        const float* p = scb + z2 * TILE_ELEMS;
        #pragma unroll
        for (int i = 0; i < 4; ++i) {
            float4 v = *reinterpret_cast<const float4*>(&p[(tr * 4 + i) * BN + tc * 4]);
            sum[i].x += v.x;  sum[i].y += v.y;  sum[i].z += v.z;  sum[i].w += v.w;
        }
    }
    #pragma unroll
    for (int i = 0; i < 4; ++i) {
        *reinterpret_cast<float4*>(&out[(row0 + tr * 4 + i) * NOUT + col0 + tc * 4]) = sum[i];
    }
}

// ---------------------------------------------------------------------------
extern "C" void kernel_launch(void* const* d_in, const int* in_sizes, int n_in,
                              void* d_out, int out_size) {
    const float* x = (const float*)d_in[0];   // (128, 1024)
    const float* w = (const float*)d_in[1];   // (1024, 512)
    const float* b = (const float*)d_in[2];   // (512,)
    float* out = (float*)d_out;               // (128, 512)

    memristor_gemm_kernel<<<dim3(NOUT / BN, BATCH / BM, SPLITK), 256>>>(x, w, b, out);
}

// round 8
// speedup vs baseline: 1.0605x; 1.0605x over previous
#include <cuda_runtime.h>

// out[128,512] = x[128,1024] @ w[1024,512] + b   (exact algebraic reduction of
// the memristor reference: G_off and the pos/neg relu split cancel in the
// even-odd column subtraction, and K_V * k_g cancels with the final divide).
//
// R8 (= R4..R7 resubmit; all infra timeouts, kernel never ran): FFMA2
// (fma.rn.f32x2) mainloop — 2 fp32 FMAs per issued instruction, halving the
// FFMA-rt floor that bound R2/R3. Single-stage smem (whole K-chunk staged
// once, ONE __syncthreads, no double buffer). x staged DUPLICATED
// (xdup[k][2m]=xdup[k][2m+1]=x[m][k]) so one LDS.128 yields two broadcast
// pairs for the packed FMA; w pairs come naturally from float4 loads.
// Deterministic split-K fixup epilogue (scratch + ticket, fixed z-order sum).

#define BATCH 128
#define NIN   1024
#define NOUT  512

#define BM 64
#define BN 64
#define SPLITK 8
#define KCHUNK (NIN / SPLITK)        // 128
#define NTILES ((BATCH / BM) * (NOUT / BN))   // 16
#define TILE_ELEMS (BM * BN)         // 4096

// padded smem row strides (floats); both 16B-aligned strides
#define XD_STRIDE 132                // xdup row: 128 dup floats + 4 pad (528B)
#define WS_STRIDE 68                 // ws  row:  64 floats + 4 pad   (272B)
#define SMEM_FLOATS (KCHUNK * XD_STRIDE + KCHUNK * WS_STRIDE)   // 25600 -> 100KB

__device__ float        g_scratch[NTILES * SPLITK * TILE_ELEMS];  // 2 MB
__device__ unsigned int g_cnt[NTILES];                            // zero-init

__device__ __forceinline__ unsigned long long ffma2(unsigned long long a,
                                                    unsigned long long b,
                                                    unsigned long long c) {
    unsigned long long d;
    asm("fma.rn.f32x2 %0, %1, %2, %3;" : "=l"(d) : "l"(a), "l"(b), "l"(c));
    return d;
}
__device__ __forceinline__ float lo32(unsigned long long v) {
    return __uint_as_float((unsigned int)v);
}
__device__ __forceinline__ float hi32(unsigned long long v) {
    return __uint_as_float((unsigned int)(v >> 32));
}

__global__ void __launch_bounds__(256, 1)
memristor_gemm_kernel(const float* __restrict__ x,
                      const float* __restrict__ w,
                      const float* __restrict__ bias,
                      float* __restrict__ out) {
    extern __shared__ float smem[];
    float* xdup = smem;                          // [KCHUNK][XD_STRIDE]
    float* ws   = smem + KCHUNK * XD_STRIDE;     // [KCHUNK][WS_STRIDE]
    __shared__ unsigned s_ret;

    const int tid   = threadIdx.x;
    const int tr    = tid >> 4;          // 0..15 -> rows tr*4..tr*4+3
    const int tc    = tid & 15;          // 0..15 -> cols tc*4..tc*4+3
    const int tileX = blockIdx.x;        // 0..7
    const int tileY = blockIdx.y;        // 0..1
    const int z     = blockIdx.z;        // 0..7
    const int tile  = tileY * (NOUT / BN) + tileX;
    const int row0  = tileY * BM;
    const int col0  = tileX * BN;
    const int kbase = z * KCHUNK;

    // ---- stage x (duplicated, k-major) ----
    // thread -> row m = tid&63, seg = tid>>6 selects a 32-float k-range.
    // 8 float4 LDGs per thread; dup-pair STS (float2) per k.
    {
        const int m   = tid & 63;
        const int seg = tid >> 6;                 // 0..3
        const float* xr = &x[(row0 + m) * NIN + kbase + seg * 32];
        float* xd = xdup + 2 * m;
        #pragma unroll
        for (int i = 0; i < 8; ++i) {
            float4 v = *reinterpret_cast<const float4*>(&xr[i * 4]);
            const int k = seg * 32 + i * 4;
            float2 d0 = make_float2(v.x, v.x);
            float2 d1 = make_float2(v.y, v.y);
            float2 d2 = make_float2(v.z, v.z);
            float2 d3 = make_float2(v.w, v.w);
            *reinterpret_cast<float2*>(&xd[(k + 0) * XD_STRIDE]) = d0;
            *reinterpret_cast<float2*>(&xd[(k + 1) * XD_STRIDE]) = d1;
            *reinterpret_cast<float2*>(&xd[(k + 2) * XD_STRIDE]) = d2;
            *reinterpret_cast<float2*>(&xd[(k + 3) * XD_STRIDE]) = d3;
        }
    }
    // ---- stage w (natural, k-major) ----
    // thread -> k-row = tid>>1, half = tid&1 (32 contiguous floats per thread)
    {
        const int kk   = tid >> 1;                // 0..127
        const int half = tid & 1;                 // 0,1
        const float* wr = &w[(kbase + kk) * NOUT + col0 + half * 32];
        float* wd = ws + kk * WS_STRIDE + half * 32;
        #pragma unroll
        for (int i = 0; i < 8; ++i) {
            float4 v = *reinterpret_cast<const float4*>(&wr[i * 4]);
            *reinterpret_cast<float4*>(&wd[i * 4]) = v;
        }
    }
    __syncthreads();

    // ---- mainloop: 128 k-steps, 8 FFMA2 + 3 LDS.128 each ----
    unsigned long long acc[4][2];
    #pragma unroll
    for (int i = 0; i < 4; ++i) { acc[i][0] = 0ull; acc[i][1] = 0ull; }

    const float* xk = xdup + tr * 8;   // dup pairs for rows tr*4..tr*4+3
    const float* wk = ws + tc * 4;     // col pairs for cols tc*4..tc*4+3

    #pragma unroll 16
    for (int k = 0; k < KCHUNK; ++k) {
        ulonglong2 ad0 = *reinterpret_cast<const ulonglong2*>(xk + k * XD_STRIDE);
        ulonglong2 ad1 = *reinterpret_cast<const ulonglong2*>(xk + k * XD_STRIDE + 4);
        ulonglong2 bp  = *reinterpret_cast<const ulonglong2*>(wk + k * WS_STRIDE);
        acc[0][0] = ffma2(ad0.x, bp.x, acc[0][0]);
        acc[0][1] = ffma2(ad0.x, bp.y, acc[0][1]);
        acc[1][0] = ffma2(ad0.y, bp.x, acc[1][0]);
        acc[1][1] = ffma2(ad0.y, bp.y, acc[1][1]);
        acc[2][0] = ffma2(ad1.x, bp.x, acc[2][0]);
        acc[2][1] = ffma2(ad1.x, bp.y, acc[2][1]);
        acc[3][0] = ffma2(ad1.y, bp.x, acc[3][0]);
        acc[3][1] = ffma2(ad1.y, bp.y, acc[3][1]);
    }

    // ---- write partial to scratch ----
    float* sc = &g_scratch[(tile * SPLITK + z) * TILE_ELEMS];
    #pragma unroll
    for (int i = 0; i < 4; ++i) {
        float4 v = make_float4(lo32(acc[i][0]), hi32(acc[i][0]),
                               lo32(acc[i][1]), hi32(acc[i][1]));
        *reinterpret_cast<float4*>(&sc[(tr * 4 + i) * BN + tc * 4]) = v;
    }
    __threadfence();

    // ---- ticket: last block per tile reduces (deterministic z-order) ----
    if (tid == 0) s_ret = atomicAdd(&g_cnt[tile], 1u);
    __syncthreads();
    if (s_ret != SPLITK - 1) return;
    if (tid == 0) *(volatile unsigned int*)&g_cnt[tile] = 0;  // reset for replay
    __threadfence();

    float4 bias4 = *reinterpret_cast<const float4*>(&bias[col0 + tc * 4]);
    float4 sum[4];
    #pragma unroll
    for (int i = 0; i < 4; ++i) sum[i] = bias4;

    const float* scb = &g_scratch[tile * SPLITK * TILE_ELEMS];
    #pragma unroll
    for (int z2 = 0; z2 < SPLITK; ++z2) {
        const float* p = scb + z2 * TILE_ELEMS;
        #pragma unroll
        for (int i = 0; i < 4; ++i) {
            float4 v = *reinterpret_cast<const float4*>(&p[(tr * 4 + i) * BN + tc * 4]);
            sum[i].x += v.x;  sum[i].y += v.y;  sum[i].z += v.z;  sum[i].w += v.w;
        }
    }
    #pragma unroll
    for (int i = 0; i < 4; ++i) {
        *reinterpret_cast<float4*>(&out[(row0 + tr * 4 + i) * NOUT + col0 + tc * 4]) = sum[i];
    }
}

// ---------------------------------------------------------------------------
extern "C" void kernel_launch(void* const* d_in, const int* in_sizes, int n_in,
                              void* d_out, int out_size) {
    const float* x = (const float*)d_in[0];   // (128, 1024)
    const float* w = (const float*)d_in[1];   // (1024, 512)
    const float* b = (const float*)d_in[2];   // (512,)
    float* out = (float*)d_out;               // (128, 512)

    // Idempotent, capture-safe host attribute set (no static guards allowed).
    cudaFuncSetAttribute(memristor_gemm_kernel,
                         cudaFuncAttributeMaxDynamicSharedMemorySize,
                         SMEM_FLOATS * (int)sizeof(float));
    memristor_gemm_kernel<<<dim3(NOUT / BN, BATCH / BM, SPLITK), 256,
                            SMEM_FLOATS * sizeof(float)>>>(x, w, b, out);
}

// round 9
// speedup vs baseline: 1.2064x; 1.1376x over previous
#include <cuda_runtime.h>
#include <cuda_bf16.h>

// out[128,512] = x[128,1024] @ w[1024,512] + b   (exact algebraic reduction of
// the memristor reference).
//
// R9: tensor-core path. FFMA2 was falsified in R8 (issue 18%, slower than
// scalar). Use mma.sync.m16n8k16.bf16 with 2-way bf16 split of fp32:
//   x = xh + xl,  w = wh + wl  (bf16 each);  x*w ~= xh*wh + xh*wl + xl*wh
// (dropped xl*wl term ~2^-16 relative). fp32 MMA accumulators -> rel_err ~1e-5.
// Grid (8,2,8)=128 blocks (one wave), 64x64 tile, K-chunk 128, ONE sync.
// w staged TRANSPOSED so B fragments are contiguous-k 32-bit LDS.
// KPAD=136 bf16 row stride -> fragment loads provably bank-conflict-free.
// Deterministic split-K fixup epilogue (scratch + ticket, fixed z-order).

#define BATCH 128
#define NIN   1024
#define NOUT  512

#define BM 64
#define BN 64
#define SPLITK 8
#define KCHUNK (NIN / SPLITK)        // 128
#define NTILES ((BATCH / BM) * (NOUT / BN))   // 16
#define TILE_ELEMS (BM * BN)         // 4096

#define KPAD 136                     // bf16 elems per smem row (272 B)
#define XH_OFF 0
#define XL_OFF (64 * KPAD)
#define WH_OFF (2 * 64 * KPAD)
#define WL_OFF (3 * 64 * KPAD)
#define SMEM_BF16 (4 * 64 * KPAD)    // 34816 elems = 69632 B

__device__ float        g_scratch[NTILES * SPLITK * TILE_ELEMS];  // 2 MB
__device__ unsigned int g_cnt[NTILES];                            // zero-init

__device__ __forceinline__ void mma_bf16(float* d, const unsigned* a,
                                         const unsigned* b) {
    asm("mma.sync.aligned.m16n8k16.row.col.f32.bf16.bf16.f32 "
        "{%0,%1,%2,%3}, {%4,%5,%6,%7}, {%8,%9}, {%0,%1,%2,%3};"
        : "+f"(d[0]), "+f"(d[1]), "+f"(d[2]), "+f"(d[3])
        : "r"(a[0]), "r"(a[1]), "r"(a[2]), "r"(a[3]), "r"(b[0]), "r"(b[1]));
}

__global__ void __launch_bounds__(256, 1)
memristor_mma_kernel(const float* __restrict__ x,
                     const float* __restrict__ w,
                     const float* __restrict__ bias,
                     float* __restrict__ out) {
    extern __shared__ __nv_bfloat16 sm[];
    __shared__ unsigned s_ret;

    const int tid  = threadIdx.x;
    const int lane = tid & 31;
    const int wid  = tid >> 5;                 // 0..7
    const int tileX = blockIdx.x;              // 0..7
    const int tileY = blockIdx.y;              // 0..1
    const int z     = blockIdx.z;              // 0..7
    const int tile  = tileY * (NOUT / BN) + tileX;
    const int row0  = tileY * BM;
    const int col0  = tileX * BN;
    const int kbase = z * KCHUNK;

    // ---- stage x -> xh, xl  (row-major, [64][KPAD] bf16 each) ----
    // thread: row r = tid>>2 (0..63), k-segment ks = (tid&3)*32
    {
        const int r  = tid >> 2;
        const int ks = (tid & 3) * 32;
        const float* xr = &x[(row0 + r) * NIN + kbase + ks];
        unsigned* hrow = reinterpret_cast<unsigned*>(sm + XH_OFF + r * KPAD + ks);
        unsigned* lrow = reinterpret_cast<unsigned*>(sm + XL_OFF + r * KPAD + ks);
        #pragma unroll
        for (int i = 0; i < 8; ++i) {
            float4 v = reinterpret_cast<const float4*>(xr)[i];
            __nv_bfloat162 h0 = __floats2bfloat162_rn(v.x, v.y);
            __nv_bfloat162 h1 = __floats2bfloat162_rn(v.z, v.w);
            float2 hf0 = __bfloat1622float2(h0);
            float2 hf1 = __bfloat1622float2(h1);
            __nv_bfloat162 l0 = __floats2bfloat162_rn(v.x - hf0.x, v.y - hf0.y);
            __nv_bfloat162 l1 = __floats2bfloat162_rn(v.z - hf1.x, v.w - hf1.y);
            hrow[i * 2 + 0] = *reinterpret_cast<unsigned*>(&h0);
            hrow[i * 2 + 1] = *reinterpret_cast<unsigned*>(&h1);
            lrow[i * 2 + 0] = *reinterpret_cast<unsigned*>(&l0);
            lrow[i * 2 + 1] = *reinterpret_cast<unsigned*>(&l1);
        }
    }
    // ---- stage w TRANSPOSED -> whT, wlT  ([64 cols][KPAD k] bf16 each) ----
    // thread: k = tid>>1 (0..127), c-segment cs = (tid&1)*32
    {
        const int k  = tid >> 1;
        const int cs = (tid & 1) * 32;
        const float* wr = &w[(kbase + k) * NOUT + col0 + cs];
        __nv_bfloat16* hT = sm + WH_OFF + k;   // + c*KPAD
        __nv_bfloat16* lT = sm + WL_OFF + k;
        #pragma unroll
        for (int i = 0; i < 8; ++i) {
            float4 v = reinterpret_cast<const float4*>(wr)[i];
            const int c = cs + i * 4;
            float vv[4] = {v.x, v.y, v.z, v.w};
            #pragma unroll
            for (int j = 0; j < 4; ++j) {
                __nv_bfloat16 h = __float2bfloat16(vv[j]);
                __nv_bfloat16 l = __float2bfloat16(vv[j] - __bfloat162float(h));
                hT[(c + j) * KPAD] = h;
                lT[(c + j) * KPAD] = l;
            }
        }
    }
    __syncthreads();

    // ---- warp tiling: 8 warps as 2 (M) x 4 (N); warp tile 32x16 ----
    const int warpM = wid >> 2;                // 0..1
    const int warpN = wid & 3;                 // 0..3
    const int group = lane >> 2;               // 0..7
    const int tig   = lane & 3;                // 0..3

    float acc[2][2][4];
    #pragma unroll
    for (int mt = 0; mt < 2; ++mt)
        #pragma unroll
        for (int nt = 0; nt < 2; ++nt)
            #pragma unroll
            for (int r = 0; r < 4; ++r) acc[mt][nt][r] = 0.0f;

    const __nv_bfloat16* xh  = sm + XH_OFF;
    const __nv_bfloat16* xl  = sm + XL_OFF;
    const __nv_bfloat16* whT = sm + WH_OFF;
    const __nv_bfloat16* wlT = sm + WL_OFF;

    #pragma unroll
    for (int ks = 0; ks < KCHUNK / 16; ++ks) {
        const int k0 = ks * 16 + tig * 2;
        unsigned ah[2][4], al[2][4], bh[2][2], bl[2][2];

        #pragma unroll
        for (int mt = 0; mt < 2; ++mt) {
            const int r0 = warpM * 32 + mt * 16 + group;
            const unsigned* h0 = reinterpret_cast<const unsigned*>(xh + r0 * KPAD + k0);
            const unsigned* h1 = reinterpret_cast<const unsigned*>(xh + (r0 + 8) * KPAD + k0);
            ah[mt][0] = h0[0]; ah[mt][1] = h1[0]; ah[mt][2] = h0[4]; ah[mt][3] = h1[4];
            const unsigned* l0 = reinterpret_cast<const unsigned*>(xl + r0 * KPAD + k0);
            const unsigned* l1 = reinterpret_cast<const unsigned*>(xl + (r0 + 8) * KPAD + k0);
            al[mt][0] = l0[0]; al[mt][1] = l1[0]; al[mt][2] = l0[4]; al[mt][3] = l1[4];
        }
        #pragma unroll
        for (int nt = 0; nt < 2; ++nt) {
            const int c0 = warpN * 16 + nt * 8 + group;
            const unsigned* bhp = reinterpret_cast<const unsigned*>(whT + c0 * KPAD + k0);
            bh[nt][0] = bhp[0]; bh[nt][1] = bhp[4];
            const unsigned* blp = reinterpret_cast<const unsigned*>(wlT + c0 * KPAD + k0);
            bl[nt][0] = blp[0]; bl[nt][1] = blp[4];
        }
        #pragma unroll
        for (int mt = 0; mt < 2; ++mt)
            #pragma unroll
            for (int nt = 0; nt < 2; ++nt) {
                mma_bf16(acc[mt][nt], ah[mt], bh[nt]);   // xh * wh
                mma_bf16(acc[mt][nt], ah[mt], bl[nt]);   // xh * wl
                mma_bf16(acc[mt][nt], al[mt], bh[nt]);   // xl * wh
            }
    }

    // ---- write partial to scratch (fragment layout -> (row, col)) ----
    float* sc = &g_scratch[(tile * SPLITK + z) * TILE_ELEMS];
    #pragma unroll
    for (int mt = 0; mt < 2; ++mt)
        #pragma unroll
        for (int nt = 0; nt < 2; ++nt) {
            const int r = warpM * 32 + mt * 16 + group;
            const int c = warpN * 16 + nt * 8 + tig * 2;
            *reinterpret_cast<float2*>(&sc[r * BN + c]) =
                make_float2(acc[mt][nt][0], acc[mt][nt][1]);
            *reinterpret_cast<float2*>(&sc[(r + 8) * BN + c]) =
                make_float2(acc[mt][nt][2], acc[mt][nt][3]);
        }
    __threadfence();

    // ---- ticket: last block per tile reduces (deterministic z-order) ----
    if (tid == 0) s_ret = atomicAdd(&g_cnt[tile], 1u);
    __syncthreads();
    if (s_ret != SPLITK - 1) return;
    if (tid == 0) *(volatile unsigned int*)&g_cnt[tile] = 0;  // reset for replay
    __threadfence();

    const int tr = tid >> 4;   // 0..15
    const int tc = tid & 15;   // 0..15
    float4 bias4 = *reinterpret_cast<const float4*>(&bias[col0 + tc * 4]);
    float4 sum[4];
    #pragma unroll
    for (int i = 0; i < 4; ++i) sum[i] = bias4;

    const float* scb = &g_scratch[tile * SPLITK * TILE_ELEMS];
    #pragma unroll
    for (int z2 = 0; z2 < SPLITK; ++z2) {
        const float* p = scb + z2 * TILE_ELEMS;
        #pragma unroll
        for (int i = 0; i < 4; ++i) {
            float4 v = *reinterpret_cast<const float4*>(&p[(tr * 4 + i) * BN + tc * 4]);
            sum[i].x += v.x;  sum[i].y += v.y;  sum[i].z += v.z;  sum[i].w += v.w;
        }
    }
    #pragma unroll
    for (int i = 0; i < 4; ++i) {
        *reinterpret_cast<float4*>(&out[(row0 + tr * 4 + i) * NOUT + col0 + tc * 4]) = sum[i];
    }
}

// ---------------------------------------------------------------------------
extern "C" void kernel_launch(void* const* d_in, const int* in_sizes, int n_in,
                              void* d_out, int out_size) {
    const float* x = (const float*)d_in[0];   // (128, 1024)
    const float* w = (const float*)d_in[1];   // (1024, 512)
    const float* b = (const float*)d_in[2];   // (512,)
    float* out = (float*)d_out;               // (128, 512)

    // Idempotent, capture-safe host attribute set (no static guards allowed).
    cudaFuncSetAttribute(memristor_mma_kernel,
                         cudaFuncAttributeMaxDynamicSharedMemorySize,
                         SMEM_BF16 * (int)sizeof(__nv_bfloat16));
    memristor_mma_kernel<<<dim3(NOUT / BN, BATCH / BM, SPLITK), 256,
                           SMEM_BF16 * sizeof(__nv_bfloat16)>>>(x, w, b, out);
}

// round 13
// speedup vs baseline: 1.4613x; 1.2113x over previous
#include <cuda_runtime.h>
#include <cuda_bf16.h>

// out[128,512] = x[128,1024] @ w[1024,512] + b   (exact algebraic reduction of
// the memristor reference).
//
// R13 (= R10..R12 resubmit; infra timeouts, never ran): latency-path trim of
// the R9 tensor kernel. Evidence: all pipes <12%, kernel dominated by serial
// chains at un-ramped clocks. Changes vs R9:
//  - ldmatrix.m8n8.x4 fragment loads (6 LDSM vs 24 LDS per k-step)
//  - w staging: coalesced scalar LDG + packed bf16x2 + conflict-free STS.128
//    (old: 64 scalar bf16 STS/thread with 4-way conflicts)
//  - fixup: syncthreads + single acq_rel atomic (drops block-wide threadfence)
// Math: 2-way bf16 split, D = xh*wh + xh*wl + xl*wh (fp32 accum).

#define BATCH 128
#define NIN   1024
#define NOUT  512

#define BM 64
#define BN 64
#define SPLITK 8
#define KCHUNK (NIN / SPLITK)        // 128
#define NTILES ((BATCH / BM) * (NOUT / BN))   // 16
#define TILE_ELEMS (BM * BN)         // 4096

#define KPAD 136                     // bf16 elems per smem row (272 B, 16B-mult)
#define KPADB (KPAD * 2)             // 272 bytes
// byte offsets of the 4 tiles ([64][KPAD] bf16 each)
#define XHB 0
#define XLB (64 * KPADB)             // 17408
#define WHB (2 * 64 * KPADB)         // 34816
#define WLB (3 * 64 * KPADB)         // 52224
#define SMEM_BYTES (4 * 64 * KPADB)  // 69632

__device__ float        g_scratch[NTILES * SPLITK * TILE_ELEMS];  // 2 MB
__device__ unsigned int g_cnt[NTILES];                            // zero-init

__device__ __forceinline__ void mma_bf16(float* d, const unsigned* a,
                                         unsigned b0, unsigned b1) {
    asm("mma.sync.aligned.m16n8k16.row.col.f32.bf16.bf16.f32 "
        "{%0,%1,%2,%3}, {%4,%5,%6,%7}, {%8,%9}, {%0,%1,%2,%3};"
        : "+f"(d[0]), "+f"(d[1]), "+f"(d[2]), "+f"(d[3])
        : "r"(a[0]), "r"(a[1]), "r"(a[2]), "r"(a[3]), "r"(b0), "r"(b1));
}

__device__ __forceinline__ void ldsm4(unsigned* r, unsigned addr) {
    asm volatile("ldmatrix.sync.aligned.m8n8.x4.shared.b16 {%0,%1,%2,%3}, [%4];"
                 : "=r"(r[0]), "=r"(r[1]), "=r"(r[2]), "=r"(r[3]) : "r"(addr));
}

__device__ __forceinline__ unsigned pack_hi(float f0, float f1,
                                            float& h0f, float& h1f) {
    __nv_bfloat162 h = __floats2bfloat162_rn(f0, f1);
    float2 hf = __bfloat1622float2(h);
    h0f = hf.x; h1f = hf.y;
    return *reinterpret_cast<unsigned*>(&h);
}

__global__ void __launch_bounds__(256, 1)
memristor_mma_kernel(const float* __restrict__ x,
                     const float* __restrict__ w,
                     const float* __restrict__ bias,
                     float* __restrict__ out) {
    extern __shared__ char sm[];
    __shared__ unsigned s_ret;

    const int tid  = threadIdx.x;
    const int lane = tid & 31;
    const int wid  = tid >> 5;                 // 0..7
    const int tileX = blockIdx.x;              // 0..7
    const int tileY = blockIdx.y;              // 0..1
    const int z     = blockIdx.z;              // 0..7
    const int tile  = tileY * (NOUT / BN) + tileX;
    const int row0  = tileY * BM;
    const int col0  = tileX * BN;
    const int kbase = z * KCHUNK;

    const unsigned smb = (unsigned)__cvta_generic_to_shared(sm);

    // ---- stage x -> xh, xl  (row-major [64][KPAD] bf16) ----
    // thread: row r = tid>>2, k-seg ks = (tid&3)*32; 8 LDG.128, 8 STS.128
    {
        const int r  = tid >> 2;
        const int ks = (tid & 3) * 32;
        const float* xr = &x[(row0 + r) * NIN + kbase + ks];
        unsigned hwd[16], lwd[16];
        #pragma unroll
        for (int i = 0; i < 8; ++i) {
            float4 v = reinterpret_cast<const float4*>(xr)[i];
            float h0, h1, h2, h3;
            hwd[2*i+0] = pack_hi(v.x, v.y, h0, h1);
            hwd[2*i+1] = pack_hi(v.z, v.w, h2, h3);
            __nv_bfloat162 l0 = __floats2bfloat162_rn(v.x - h0, v.y - h1);
            __nv_bfloat162 l1 = __floats2bfloat162_rn(v.z - h2, v.w - h3);
            lwd[2*i+0] = *reinterpret_cast<unsigned*>(&l0);
            lwd[2*i+1] = *reinterpret_cast<unsigned*>(&l1);
        }
        uint4* hdst = reinterpret_cast<uint4*>(sm + XHB + r * KPADB + ks * 2);
        uint4* ldst = reinterpret_cast<uint4*>(sm + XLB + r * KPADB + ks * 2);
        #pragma unroll
        for (int i = 0; i < 4; ++i) {
            hdst[i] = make_uint4(hwd[4*i], hwd[4*i+1], hwd[4*i+2], hwd[4*i+3]);
            ldst[i] = make_uint4(lwd[4*i], lwd[4*i+1], lwd[4*i+2], lwd[4*i+3]);
        }
    }
    // ---- stage w TRANSPOSED -> whT, wlT  ([64 c][KPAD k] bf16) ----
    // thread: col c = tid&63, quad base q0 = (tid>>6)*4; per quad: 8 coalesced
    // LDG.32 (k rows), pack 4 hi + 4 lo bf16x2 words, 2 STS.128.
    {
        const int c  = tid & 63;
        const int q0 = (tid >> 6) * 4;
        const float* wc = &w[kbase * NOUT + col0 + c];
        #pragma unroll
        for (int j = 0; j < 4; ++j) {
            const int k0 = (q0 + j) * 8;
            float f[8];
            #pragma unroll
            for (int e = 0; e < 8; ++e) f[e] = wc[(k0 + e) * NOUT];
            unsigned hw[4], lw[4];
            #pragma unroll
            for (int p = 0; p < 4; ++p) {
                float h0, h1;
                hw[p] = pack_hi(f[2*p], f[2*p+1], h0, h1);
                __nv_bfloat162 l = __floats2bfloat162_rn(f[2*p] - h0, f[2*p+1] - h1);
                lw[p] = *reinterpret_cast<unsigned*>(&l);
            }
            *reinterpret_cast<uint4*>(sm + WHB + c * KPADB + k0 * 2) =
                make_uint4(hw[0], hw[1], hw[2], hw[3]);
            *reinterpret_cast<uint4*>(sm + WLB + c * KPADB + k0 * 2) =
                make_uint4(lw[0], lw[1], lw[2], lw[3]);
        }
    }
    __syncthreads();

    // ---- warp tiling: 2 (M) x 4 (N), warp tile 32x16 ----
    const int warpM = wid >> 2;                // 0..1
    const int warpN = wid & 3;                 // 0..3
    const int group = lane >> 2;               // 0..7
    const int tig   = lane & 3;                // 0..3

    // ldmatrix lane offset: (row-in-8) + (+8 rows for lanes 8-15/24-31),
    // +16B (k+8) for lanes 16-31
    const unsigned loff = ((lane & 7) + ((lane >> 3) & 1) * 8) * KPADB
                        + ((lane >> 4) * 16);

    unsigned ahb0 = smb + XHB + (warpM * 32 +  0) * KPADB + loff;
    unsigned ahb1 = smb + XHB + (warpM * 32 + 16) * KPADB + loff;
    unsigned alb0 = smb + XLB + (warpM * 32 +  0) * KPADB + loff;
    unsigned alb1 = smb + XLB + (warpM * 32 + 16) * KPADB + loff;
    unsigned bhb  = smb + WHB + (warpN * 16) * KPADB + loff;
    unsigned blb  = smb + WLB + (warpN * 16) * KPADB + loff;

    float acc[2][2][4] = {};

    #pragma unroll
    for (int ks = 0; ks < KCHUNK / 16; ++ks) {
        const unsigned kb = ks * 32;           // 16 bf16 = 32 bytes
        unsigned ah0[4], ah1[4], al0[4], al1[4], bh[4], bl[4];
        ldsm4(ah0, ahb0 + kb);
        ldsm4(ah1, ahb1 + kb);
        ldsm4(al0, alb0 + kb);
        ldsm4(al1, alb1 + kb);
        ldsm4(bh,  bhb  + kb);                 // {nt0_k0, nt1_k0, nt0_k1, nt1_k1}
        ldsm4(bl,  blb  + kb);

        mma_bf16(acc[0][0], ah0, bh[0], bh[2]);
        mma_bf16(acc[0][1], ah0, bh[1], bh[3]);
        mma_bf16(acc[1][0], ah1, bh[0], bh[2]);
        mma_bf16(acc[1][1], ah1, bh[1], bh[3]);

        mma_bf16(acc[0][0], ah0, bl[0], bl[2]);
        mma_bf16(acc[0][1], ah0, bl[1], bl[3]);
        mma_bf16(acc[1][0], ah1, bl[0], bl[2]);
        mma_bf16(acc[1][1], ah1, bl[1], bl[3]);

        mma_bf16(acc[0][0], al0, bh[0], bh[2]);
        mma_bf16(acc[0][1], al0, bh[1], bh[3]);
        mma_bf16(acc[1][0], al1, bh[0], bh[2]);
        mma_bf16(acc[1][1], al1, bh[1], bh[3]);
    }

    // ---- write partial to scratch ----
    float* sc = &g_scratch[(tile * SPLITK + z) * TILE_ELEMS];
    #pragma unroll
    for (int mt = 0; mt < 2; ++mt)
        #pragma unroll
        for (int nt = 0; nt < 2; ++nt) {
            const int r = warpM * 32 + mt * 16 + group;
            const int c = warpN * 16 + nt * 8 + tig * 2;
            *reinterpret_cast<float2*>(&sc[r * BN + c]) =
                make_float2(acc[mt][nt][0], acc[mt][nt][1]);
            *reinterpret_cast<float2*>(&sc[(r + 8) * BN + c]) =
                make_float2(acc[mt][nt][2], acc[mt][nt][3]);
        }

    // ---- ticket: bar.sync orders block writes; acq_rel atomic publishes ----
    __syncthreads();
    if (tid == 0) {
        unsigned old;
        asm volatile("atom.acq_rel.gpu.global.add.u32 %0, [%1], 1;"
                     : "=r"(old) : "l"(&g_cnt[tile]) : "memory");
        s_ret = old;
    }
    __syncthreads();
    if (s_ret != SPLITK - 1) return;
    if (tid == 0) *(volatile unsigned int*)&g_cnt[tile] = 0;  // reset for replay

    // ---- deterministic reduction: bias + fixed z-order sum ----
    const int tr = tid >> 4;   // 0..15
    const int tc = tid & 15;   // 0..15
    float4 bias4 = *reinterpret_cast<const float4*>(&bias[col0 + tc * 4]);
    float4 sum[4];
    #pragma unroll
    for (int i = 0; i < 4; ++i) sum[i] = bias4;

    const float* scb = &g_scratch[tile * SPLITK * TILE_ELEMS];
    #pragma unroll
    for (int z2 = 0; z2 < SPLITK; ++z2) {
        const float* p = scb + z2 * TILE_ELEMS;
        #pragma unroll
        for (int i = 0; i < 4; ++i) {
            float4 v = *reinterpret_cast<const float4*>(&p[(tr * 4 + i) * BN + tc * 4]);
            sum[i].x += v.x;  sum[i].y += v.y;  sum[i].z += v.z;  sum[i].w += v.w;
        }
    }
    #pragma unroll
    for (int i = 0; i < 4; ++i) {
        *reinterpret_cast<float4*>(&out[(row0 + tr * 4 + i) * NOUT + col0 + tc * 4]) = sum[i];
    }
}

// ---------------------------------------------------------------------------
extern "C" void kernel_launch(void* const* d_in, const int* in_sizes, int n_in,
                              void* d_out, int out_size) {
    const float* x = (const float*)d_in[0];   // (128, 1024)
    const float* w = (const float*)d_in[1];   // (1024, 512)
    const float* b = (const float*)d_in[2];   // (512,)
    float* out = (float*)d_out;               // (128, 512)

    cudaFuncSetAttribute(memristor_mma_kernel,
                         cudaFuncAttributeMaxDynamicSharedMemorySize, SMEM_BYTES);
    memristor_mma_kernel<<<dim3(NOUT / BN, BATCH / BM, SPLITK), 256, SMEM_BYTES>>>(
        x, w, b, out);
}